// round 6
// baseline (speedup 1.0000x reference)
#include <cuda_runtime.h>
#include <math.h>

#define F_IN   512
#define HID    16
#define CLS    40
#define N_MAX  100000
#define E_MAX  3400000

// ---------------- scratch (static device globals; no allocation) ------------
__device__ float  g_dis[N_MAX];                 // deg -> dis = rsqrt(deg)
__device__ int    g_cnt[N_MAX];                 // in-degree counts
__device__ int    g_off[N_MAX + 1];             // CSR offsets (by col)
__device__ int    g_cursor[N_MAX];              // fill cursors
__device__ unsigned long long g_csr[E_MAX];     // packed (norm<<32 | row)
__device__ float4 g_h1[N_MAX * 4];              // h1, later reused for t
__device__ float4 g_h2[N_MAX * 4];              // r = relu(layer1)

// ---------------- f32x2 packed math helpers (sm_10x FFMA2) ------------------
__device__ __forceinline__ unsigned long long pack2(float lo, float hi) {
    unsigned long long d;
    asm("mov.b64 %0, {%1,%2};" : "=l"(d) : "f"(lo), "f"(hi));
    return d;
}
__device__ __forceinline__ void unpack2(unsigned long long v, float& lo, float& hi) {
    asm("mov.b64 {%0,%1}, %2;" : "=f"(lo), "=f"(hi) : "l"(v));
}
__device__ __forceinline__ unsigned long long fma2(unsigned long long a,
                                                   unsigned long long b,
                                                   unsigned long long c) {
    unsigned long long d;
    asm("fma.rn.f32x2 %0, %1, %2, %3;" : "=l"(d) : "l"(a), "l"(b), "l"(c));
    return d;
}

// ---------------- init: dis=1 (self-loop weight), cnt=0 ---------------------
__global__ void init_kernel(int N) {
    int i = blockIdx.x * blockDim.x + threadIdx.x;
    if (i < N) { g_dis[i] = 1.0f; g_cnt[i] = 0; }
}

// deg[col] += w ; cnt[col] += 1
__global__ void deg_kernel(const int* __restrict__ col, const float* __restrict__ w, int E) {
    int e = blockIdx.x * blockDim.x + threadIdx.x;
    if (e < E) {
        int c = col[e];
        atomicAdd(&g_dis[c], w[e]);
        atomicAdd(&g_cnt[c], 1);
    }
}

// dis = rsqrt(deg)
__global__ void dis_kernel(int N) {
    int i = blockIdx.x * blockDim.x + threadIdx.x;
    if (i < N) g_dis[i] = rsqrtf(fmaxf(g_dis[i], 1e-12f));
}

// single-block exclusive scan of g_cnt -> g_off, g_cursor
__global__ void scan_kernel(int N) {
    __shared__ int ssum[1024];
    int t = threadIdx.x;
    int chunk = (N + 1023) / 1024;
    int beg = t * chunk;
    int end = min(beg + chunk, N);
    int s = 0;
    for (int i = beg; i < end; i++) s += g_cnt[i];
    ssum[t] = s;
    __syncthreads();
    for (int d = 1; d < 1024; d <<= 1) {
        int v = (t >= d) ? ssum[t - d] : 0;
        __syncthreads();
        ssum[t] += v;
        __syncthreads();
    }
    int base = (t == 0) ? 0 : ssum[t - 1];
    for (int i = beg; i < end; i++) {
        g_off[i] = base;
        g_cursor[i] = base;
        base += g_cnt[i];
    }
    if (t == 1023) g_off[N] = ssum[1023];
}

// fill CSR: for each edge, norm = dis[r]*w*dis[c], append (r, norm) to col c
__global__ void fill_kernel(const int* __restrict__ ei, const float* __restrict__ w, int E) {
    int e = blockIdx.x * blockDim.x + threadIdx.x;
    if (e >= E) return;
    int r = ei[e];
    int c = ei[E + e];
    float nrm = g_dis[r] * w[e] * g_dis[c];
    int pos = atomicAdd(&g_cursor[c], 1);
    g_csr[pos] = ((unsigned long long)__float_as_uint(nrm) << 32) | (unsigned int)r;
}

// ---------------- dense GEMM: h1 = x @ W1 (f32x2 packed FFMA) ---------------
#define GT    64      // threads per block
#define GR    4       // rows per thread (2 packed pairs)
#define GROWS (GT*GR) // 256 rows per block
#define KC    16      // k-chunk

__global__ __launch_bounds__(GT) void gemm1_kernel(const float* __restrict__ x,
                                                   const float* __restrict__ W1,
                                                   int N) {
    __shared__ float xs[GROWS][KC + 1];            // +1 pad: bank-conflict-free
    __shared__ unsigned long long ws2[KC][HID];    // W duplicated (w,w)
    int r0 = blockIdx.x * GROWS;

    unsigned long long acc2[2][HID];
    #pragma unroll
    for (int p = 0; p < 2; p++)
        #pragma unroll
        for (int j = 0; j < HID; j++) acc2[p][j] = 0ULL;

    for (int kc = 0; kc < F_IN; kc += KC) {
        __syncthreads();
        for (int i = threadIdx.x; i < KC * HID; i += GT) {
            float wv = W1[(kc + i / HID) * HID + (i % HID)];
            ws2[i / HID][i % HID] = pack2(wv, wv);
        }
        for (int idx = threadIdx.x; idx < GROWS * (KC / 4); idx += GT) {
            int rl  = idx / (KC / 4);
            int c4  = idx % (KC / 4);
            int row = r0 + rl;
            float4 v = make_float4(0.f, 0.f, 0.f, 0.f);
            if (row < N)
                v = *(const float4*)(x + (size_t)row * F_IN + kc + c4 * 4);
            xs[rl][c4 * 4 + 0] = v.x;
            xs[rl][c4 * 4 + 1] = v.y;
            xs[rl][c4 * 4 + 2] = v.z;
            xs[rl][c4 * 4 + 3] = v.w;
        }
        __syncthreads();

        #pragma unroll 4
        for (int kk = 0; kk < KC; kk++) {
            unsigned long long wv[HID];
            #pragma unroll
            for (int j = 0; j < HID; j++) wv[j] = ws2[kk][j];
            #pragma unroll
            for (int p = 0; p < 2; p++) {
                float xa = xs[threadIdx.x + (2 * p + 0) * GT][kk];
                float xb = xs[threadIdx.x + (2 * p + 1) * GT][kk];
                unsigned long long xp = pack2(xa, xb);
                #pragma unroll
                for (int j = 0; j < HID; j++)
                    acc2[p][j] = fma2(xp, wv[j], acc2[p][j]);
            }
        }
    }

    #pragma unroll
    for (int p = 0; p < 2; p++) {
        float va[HID], vb[HID];
        #pragma unroll
        for (int j = 0; j < HID; j++) unpack2(acc2[p][j], va[j], vb[j]);
        int rowA = r0 + threadIdx.x + (2 * p + 0) * GT;
        int rowB = r0 + threadIdx.x + (2 * p + 1) * GT;
        if (rowA < N) {
            #pragma unroll
            for (int q = 0; q < 4; q++)
                g_h1[rowA * 4 + q] = make_float4(va[4*q], va[4*q+1], va[4*q+2], va[4*q+3]);
        }
        if (rowB < N) {
            #pragma unroll
            for (int q = 0; q < 4; q++)
                g_h1[rowB * 4 + q] = make_float4(vb[4*q], vb[4*q+1], vb[4*q+2], vb[4*q+3]);
        }
    }
}

// ---------------- CSR gather aggregation (warp per node, no atomics) --------
// LAYER 1: dst = relu(sum_edges + dis^2*src[node] + b1)   (g_h1 -> g_h2)
// LAYER 2: dst = sum_edges + dis^2*src[node]              (g_h2 -> g_h1)
template<int LAYER>
__global__ __launch_bounds__(256) void gather_kernel(const float* __restrict__ bias, int N) {
    const float4* __restrict__ src = (LAYER == 1) ? g_h1 : g_h2;
    float4* __restrict__ dst       = (LAYER == 1) ? g_h2 : g_h1;

    int node = (blockIdx.x * blockDim.x + threadIdx.x) >> 5;
    int lane = threadIdx.x & 31;
    if (node >= N) return;

    int start = g_off[node];
    int end   = g_off[node + 1];
    int sub = lane >> 2;     // 0..7 : edge slot
    int q   = lane & 3;      // 0..3 : float4 quad

    float4 acc = make_float4(0.f, 0.f, 0.f, 0.f);
    for (int e = start + sub; e < end; e += 8) {
        unsigned long long en = g_csr[e];
        int   r   = (int)(unsigned int)(en & 0xffffffffULL);
        float nrm = __uint_as_float((unsigned int)(en >> 32));
        float4 s = src[r * 4 + q];
        acc.x = fmaf(nrm, s.x, acc.x);
        acc.y = fmaf(nrm, s.y, acc.y);
        acc.z = fmaf(nrm, s.z, acc.z);
        acc.w = fmaf(nrm, s.w, acc.w);
    }
    // reduce across the 8 edge-slots (same q)
    #pragma unroll
    for (int m = 4; m < 32; m <<= 1) {
        acc.x += __shfl_xor_sync(0xffffffffu, acc.x, m);
        acc.y += __shfl_xor_sync(0xffffffffu, acc.y, m);
        acc.z += __shfl_xor_sync(0xffffffffu, acc.z, m);
        acc.w += __shfl_xor_sync(0xffffffffu, acc.w, m);
    }
    if (lane < 4) {
        float d  = g_dis[node];
        float d2 = d * d;
        float4 h = src[node * 4 + lane];        // self loop: dis^2 * h[node]
        acc.x = fmaf(d2, h.x, acc.x);
        acc.y = fmaf(d2, h.y, acc.y);
        acc.z = fmaf(d2, h.z, acc.z);
        acc.w = fmaf(d2, h.w, acc.w);
        if (LAYER == 1) {
            float4 b = ((const float4*)bias)[lane];
            acc.x = fmaxf(acc.x + b.x, 0.f);
            acc.y = fmaxf(acc.y + b.y, 0.f);
            acc.z = fmaxf(acc.z + b.z, 0.f);
            acc.w = fmaxf(acc.w + b.w, 0.f);
        }
        dst[node * 4 + lane] = acc;
    }
}

// ---------------- epilogue: t @ W2 + b2 -> log_softmax ----------------------
__global__ __launch_bounds__(128) void final_kernel(const float* __restrict__ W2,
                                                    const float* __restrict__ b2,
                                                    float* __restrict__ out,
                                                    int N) {
    __shared__ float w2s[HID][CLS];
    __shared__ float b2s[CLS];
    for (int i = threadIdx.x; i < HID * CLS; i += blockDim.x)
        w2s[i / CLS][i % CLS] = W2[i];
    if (threadIdx.x < CLS) b2s[threadIdx.x] = b2[threadIdx.x];
    __syncthreads();

    int i = blockIdx.x * blockDim.x + threadIdx.x;
    if (i >= N) return;

    float t[HID];
    #pragma unroll
    for (int q = 0; q < 4; q++) {
        float4 v = g_h1[i * 4 + q];     // t lives in g_h1 after gather<2>
        t[4*q+0] = v.x; t[4*q+1] = v.y; t[4*q+2] = v.z; t[4*q+3] = v.w;
    }

    float acc[CLS];
    #pragma unroll
    for (int j = 0; j < CLS; j++) acc[j] = b2s[j];
    #pragma unroll
    for (int k = 0; k < HID; k++) {
        float tv = t[k];
        #pragma unroll
        for (int j = 0; j < CLS; j++)
            acc[j] = fmaf(tv, w2s[k][j], acc[j]);
    }

    float m = acc[0];
    #pragma unroll
    for (int j = 1; j < CLS; j++) m = fmaxf(m, acc[j]);
    float s = 0.f;
    #pragma unroll
    for (int j = 0; j < CLS; j++) s += expf(acc[j] - m);
    float lse = m + logf(s);

    float* o = out + (size_t)i * CLS;
    #pragma unroll
    for (int q = 0; q < CLS / 4; q++) {
        float4 v = make_float4(acc[4*q+0] - lse, acc[4*q+1] - lse,
                               acc[4*q+2] - lse, acc[4*q+3] - lse);
        *(float4*)(o + 4 * q) = v;
    }
}

// ---------------------------------------------------------------------------
extern "C" void kernel_launch(void* const* d_in, const int* in_sizes, int n_in,
                              void* d_out, int out_size) {
    const float* x  = (const float*)d_in[0];
    const int*   ei = (const int*)d_in[1];
    const float* ew = (const float*)d_in[2];
    const float* W1 = (const float*)d_in[3];
    const float* b1 = (const float*)d_in[4];
    const float* W2 = (const float*)d_in[5];
    const float* b2 = (const float*)d_in[6];
    float* out = (float*)d_out;

    int N = in_sizes[0] / F_IN;     // 100000
    int E = in_sizes[2];            // 3200000

    const int T = 256;
    init_kernel<<<(N + T - 1) / T, T>>>(N);
    deg_kernel<<<(E + T - 1) / T, T>>>(ei + E, ew, E);
    dis_kernel<<<(N + T - 1) / T, T>>>(N);
    scan_kernel<<<1, 1024>>>(N);
    fill_kernel<<<(E + T - 1) / T, T>>>(ei, ew, E);
    gemm1_kernel<<<(N + GROWS - 1) / GROWS, GT>>>(x, W1, N);
    gather_kernel<1><<<(N * 32 + T - 1) / T, T>>>(b1, N);
    gather_kernel<2><<<(N * 32 + T - 1) / T, T>>>(nullptr, N);
    final_kernel<<<(N + 127) / 128, 128>>>(W2, b2, out, N);
}

// round 7
// speedup vs baseline: 1.4257x; 1.4257x over previous
#include <cuda_runtime.h>
#include <math.h>

#define F_IN   512
#define HID    16
#define CLS    40
#define N_MAX  100000
#define E_MAX  3400000
#define SCAN_B 1024
#define NBLK   ((N_MAX + SCAN_B - 1) / SCAN_B)   // 98

// ---------------- scratch (static device globals; no allocation) ------------
__device__ float  g_dis[N_MAX];                 // deg -> dis = rsqrt(deg)
__device__ int    g_cnt[N_MAX];                 // in-degree counts
__device__ int    g_off[N_MAX + 1];             // CSR offsets (by col)
__device__ int    g_cursor[N_MAX];              // fill cursors
__device__ int    g_bsum[NBLK];                 // per-block totals
__device__ int    g_boff[NBLK];                 // per-block exclusive offsets
__device__ unsigned long long g_csr[E_MAX];     // packed (norm<<32 | row)
__device__ float4 g_h1[N_MAX * 4];              // h1, later reused for t
__device__ float4 g_h2[N_MAX * 4];              // r = relu(layer1)

// ---------------- f32x2 packed math helpers (sm_10x FFMA2) ------------------
__device__ __forceinline__ unsigned long long pack2(float lo, float hi) {
    unsigned long long d;
    asm("mov.b64 %0, {%1,%2};" : "=l"(d) : "f"(lo), "f"(hi));
    return d;
}
__device__ __forceinline__ void unpack2(unsigned long long v, float& lo, float& hi) {
    asm("mov.b64 {%0,%1}, %2;" : "=f"(lo), "=f"(hi) : "l"(v));
}
__device__ __forceinline__ unsigned long long fma2(unsigned long long a,
                                                   unsigned long long b,
                                                   unsigned long long c) {
    unsigned long long d;
    asm("fma.rn.f32x2 %0, %1, %2, %3;" : "=l"(d) : "l"(a), "l"(b), "l"(c));
    return d;
}

// ---------------- init: dis=1 (self-loop weight), cnt=0 ---------------------
__global__ void init_kernel(int N) {
    int i = blockIdx.x * blockDim.x + threadIdx.x;
    if (i < N) { g_dis[i] = 1.0f; g_cnt[i] = 0; }
}

// deg[col] += w ; cnt[col] += 1
__global__ void deg_kernel(const int* __restrict__ col, const float* __restrict__ w, int E) {
    int e = blockIdx.x * blockDim.x + threadIdx.x;
    if (e < E) {
        int c = col[e];
        atomicAdd(&g_dis[c], w[e]);
        atomicAdd(&g_cnt[c], 1);
    }
}

// dis = rsqrt(deg)
__global__ void dis_kernel(int N) {
    int i = blockIdx.x * blockDim.x + threadIdx.x;
    if (i < N) g_dis[i] = rsqrtf(fmaxf(g_dis[i], 1e-12f));
}

// ---------------- 3-phase multi-block exclusive scan ------------------------
// phase 1: per-block exclusive scan of g_cnt into g_off; totals -> g_bsum
__global__ __launch_bounds__(SCAN_B) void scan1_kernel(int N) {
    __shared__ int s[SCAN_B];
    int t = threadIdx.x;
    int i = blockIdx.x * SCAN_B + t;
    int v = (i < N) ? g_cnt[i] : 0;
    s[t] = v;
    __syncthreads();
    #pragma unroll
    for (int d = 1; d < SCAN_B; d <<= 1) {
        int u = (t >= d) ? s[t - d] : 0;
        __syncthreads();
        s[t] += u;
        __syncthreads();
    }
    if (i < N) g_off[i] = s[t] - v;                 // exclusive
    if (t == SCAN_B - 1) g_bsum[blockIdx.x] = s[t]; // block total
}

// phase 2: single small block scans the 98 block totals (exclusive)
__global__ __launch_bounds__(128) void scan2_kernel(int N) {
    __shared__ int s[128];
    int t = threadIdx.x;
    int v = (t < NBLK) ? g_bsum[t] : 0;
    s[t] = v;
    __syncthreads();
    #pragma unroll
    for (int d = 1; d < 128; d <<= 1) {
        int u = (t >= d) ? s[t - d] : 0;
        __syncthreads();
        s[t] += u;
        __syncthreads();
    }
    if (t < NBLK) g_boff[t] = s[t] - v;
    if (t == 127) g_off[N] = s[t];                  // grand total (= E)
}

// phase 3: add block offsets; init cursors
__global__ void scan3_kernel(int N) {
    int i = blockIdx.x * blockDim.x + threadIdx.x;
    if (i < N) {
        int o = g_off[i] + g_boff[i / SCAN_B];
        g_off[i] = o;
        g_cursor[i] = o;
    }
}

// fill CSR: for each edge, norm = dis[r]*w*dis[c], append (r, norm) to col c
__global__ void fill_kernel(const int* __restrict__ ei, const float* __restrict__ w, int E) {
    int e = blockIdx.x * blockDim.x + threadIdx.x;
    if (e >= E) return;
    int r = ei[e];
    int c = ei[E + e];
    float nrm = g_dis[r] * w[e] * g_dis[c];
    int pos = atomicAdd(&g_cursor[c], 1);
    g_csr[pos] = ((unsigned long long)__float_as_uint(nrm) << 32) | (unsigned int)r;
}

// ---------------- dense GEMM: h1 = x @ W1 (f32x2 packed FFMA) ---------------
#define GT    64      // threads per block
#define GR    4       // rows per thread (2 packed pairs)
#define GROWS (GT*GR) // 256 rows per block
#define KC    16      // k-chunk

__global__ __launch_bounds__(GT) void gemm1_kernel(const float* __restrict__ x,
                                                   const float* __restrict__ W1,
                                                   int N) {
    __shared__ float xs[GROWS][KC + 1];            // +1 pad: bank-conflict-free
    __shared__ unsigned long long ws2[KC][HID];    // W duplicated (w,w)
    int r0 = blockIdx.x * GROWS;

    unsigned long long acc2[2][HID];
    #pragma unroll
    for (int p = 0; p < 2; p++)
        #pragma unroll
        for (int j = 0; j < HID; j++) acc2[p][j] = 0ULL;

    for (int kc = 0; kc < F_IN; kc += KC) {
        __syncthreads();
        for (int i = threadIdx.x; i < KC * HID; i += GT) {
            float wv = W1[(kc + i / HID) * HID + (i % HID)];
            ws2[i / HID][i % HID] = pack2(wv, wv);
        }
        for (int idx = threadIdx.x; idx < GROWS * (KC / 4); idx += GT) {
            int rl  = idx / (KC / 4);
            int c4  = idx % (KC / 4);
            int row = r0 + rl;
            float4 v = make_float4(0.f, 0.f, 0.f, 0.f);
            if (row < N)
                v = *(const float4*)(x + (size_t)row * F_IN + kc + c4 * 4);
            xs[rl][c4 * 4 + 0] = v.x;
            xs[rl][c4 * 4 + 1] = v.y;
            xs[rl][c4 * 4 + 2] = v.z;
            xs[rl][c4 * 4 + 3] = v.w;
        }
        __syncthreads();

        #pragma unroll 4
        for (int kk = 0; kk < KC; kk++) {
            unsigned long long wv[HID];
            #pragma unroll
            for (int j = 0; j < HID; j++) wv[j] = ws2[kk][j];
            #pragma unroll
            for (int p = 0; p < 2; p++) {
                float xa = xs[threadIdx.x + (2 * p + 0) * GT][kk];
                float xb = xs[threadIdx.x + (2 * p + 1) * GT][kk];
                unsigned long long xp = pack2(xa, xb);
                #pragma unroll
                for (int j = 0; j < HID; j++)
                    acc2[p][j] = fma2(xp, wv[j], acc2[p][j]);
            }
        }
    }

    #pragma unroll
    for (int p = 0; p < 2; p++) {
        float va[HID], vb[HID];
        #pragma unroll
        for (int j = 0; j < HID; j++) unpack2(acc2[p][j], va[j], vb[j]);
        int rowA = r0 + threadIdx.x + (2 * p + 0) * GT;
        int rowB = r0 + threadIdx.x + (2 * p + 1) * GT;
        if (rowA < N) {
            #pragma unroll
            for (int q = 0; q < 4; q++)
                g_h1[rowA * 4 + q] = make_float4(va[4*q], va[4*q+1], va[4*q+2], va[4*q+3]);
        }
        if (rowB < N) {
            #pragma unroll
            for (int q = 0; q < 4; q++)
                g_h1[rowB * 4 + q] = make_float4(vb[4*q], vb[4*q+1], vb[4*q+2], vb[4*q+3]);
        }
    }
}

// ---------------- CSR gather aggregation (warp per node, no atomics) --------
// LAYER 1: dst = relu(sum_edges + dis^2*src[node] + b1)   (g_h1 -> g_h2)
// LAYER 2: dst = sum_edges + dis^2*src[node]              (g_h2 -> g_h1)
template<int LAYER>
__global__ __launch_bounds__(256) void gather_kernel(const float* __restrict__ bias, int N) {
    const float4* __restrict__ src = (LAYER == 1) ? g_h1 : g_h2;
    float4* __restrict__ dst       = (LAYER == 1) ? g_h2 : g_h1;

    int node = (blockIdx.x * blockDim.x + threadIdx.x) >> 5;
    int lane = threadIdx.x & 31;
    if (node >= N) return;

    int start = g_off[node];
    int end   = g_off[node + 1];
    int sub = lane >> 2;     // 0..7 : edge slot
    int q   = lane & 3;      // 0..3 : float4 quad

    float4 acc = make_float4(0.f, 0.f, 0.f, 0.f);
    for (int e = start + sub; e < end; e += 8) {
        unsigned long long en = g_csr[e];
        int   r   = (int)(unsigned int)(en & 0xffffffffULL);
        float nrm = __uint_as_float((unsigned int)(en >> 32));
        float4 s = src[r * 4 + q];
        acc.x = fmaf(nrm, s.x, acc.x);
        acc.y = fmaf(nrm, s.y, acc.y);
        acc.z = fmaf(nrm, s.z, acc.z);
        acc.w = fmaf(nrm, s.w, acc.w);
    }
    // reduce across the 8 edge-slots (same q)
    #pragma unroll
    for (int m = 4; m < 32; m <<= 1) {
        acc.x += __shfl_xor_sync(0xffffffffu, acc.x, m);
        acc.y += __shfl_xor_sync(0xffffffffu, acc.y, m);
        acc.z += __shfl_xor_sync(0xffffffffu, acc.z, m);
        acc.w += __shfl_xor_sync(0xffffffffu, acc.w, m);
    }
    if (lane < 4) {
        float d  = g_dis[node];
        float d2 = d * d;
        float4 h = src[node * 4 + lane];        // self loop: dis^2 * h[node]
        acc.x = fmaf(d2, h.x, acc.x);
        acc.y = fmaf(d2, h.y, acc.y);
        acc.z = fmaf(d2, h.z, acc.z);
        acc.w = fmaf(d2, h.w, acc.w);
        if (LAYER == 1) {
            float4 b = ((const float4*)bias)[lane];
            acc.x = fmaxf(acc.x + b.x, 0.f);
            acc.y = fmaxf(acc.y + b.y, 0.f);
            acc.z = fmaxf(acc.z + b.z, 0.f);
            acc.w = fmaxf(acc.w + b.w, 0.f);
        }
        dst[node * 4 + lane] = acc;
    }
}

// ---------------- epilogue: t @ W2 + b2 -> log_softmax ----------------------
__global__ __launch_bounds__(128) void final_kernel(const float* __restrict__ W2,
                                                    const float* __restrict__ b2,
                                                    float* __restrict__ out,
                                                    int N) {
    __shared__ float w2s[HID][CLS];
    __shared__ float b2s[CLS];
    for (int i = threadIdx.x; i < HID * CLS; i += blockDim.x)
        w2s[i / CLS][i % CLS] = W2[i];
    if (threadIdx.x < CLS) b2s[threadIdx.x] = b2[threadIdx.x];
    __syncthreads();

    int i = blockIdx.x * blockDim.x + threadIdx.x;
    if (i >= N) return;

    float t[HID];
    #pragma unroll
    for (int q = 0; q < 4; q++) {
        float4 v = g_h1[i * 4 + q];     // t lives in g_h1 after gather<2>
        t[4*q+0] = v.x; t[4*q+1] = v.y; t[4*q+2] = v.z; t[4*q+3] = v.w;
    }

    float acc[CLS];
    #pragma unroll
    for (int j = 0; j < CLS; j++) acc[j] = b2s[j];
    #pragma unroll
    for (int k = 0; k < HID; k++) {
        float tv = t[k];
        #pragma unroll
        for (int j = 0; j < CLS; j++)
            acc[j] = fmaf(tv, w2s[k][j], acc[j]);
    }

    float m = acc[0];
    #pragma unroll
    for (int j = 1; j < CLS; j++) m = fmaxf(m, acc[j]);
    float s = 0.f;
    #pragma unroll
    for (int j = 0; j < CLS; j++) s += expf(acc[j] - m);
    float lse = m + logf(s);

    float* o = out + (size_t)i * CLS;
    #pragma unroll
    for (int q = 0; q < CLS / 4; q++) {
        float4 v = make_float4(acc[4*q+0] - lse, acc[4*q+1] - lse,
                               acc[4*q+2] - lse, acc[4*q+3] - lse);
        *(float4*)(o + 4 * q) = v;
    }
}

// ---------------------------------------------------------------------------
extern "C" void kernel_launch(void* const* d_in, const int* in_sizes, int n_in,
                              void* d_out, int out_size) {
    const float* x  = (const float*)d_in[0];
    const int*   ei = (const int*)d_in[1];
    const float* ew = (const float*)d_in[2];
    const float* W1 = (const float*)d_in[3];
    const float* b1 = (const float*)d_in[4];
    const float* W2 = (const float*)d_in[5];
    const float* b2 = (const float*)d_in[6];
    float* out = (float*)d_out;

    int N = in_sizes[0] / F_IN;     // 100000
    int E = in_sizes[2];            // 3200000

    const int T = 256;
    init_kernel<<<(N + T - 1) / T, T>>>(N);
    deg_kernel<<<(E + T - 1) / T, T>>>(ei + E, ew, E);
    dis_kernel<<<(N + T - 1) / T, T>>>(N);
    scan1_kernel<<<NBLK, SCAN_B>>>(N);
    scan2_kernel<<<1, 128>>>(N);
    scan3_kernel<<<(N + T - 1) / T, T>>>(N);
    fill_kernel<<<(E + T - 1) / T, T>>>(ei, ew, E);
    gemm1_kernel<<<(N + GROWS - 1) / GROWS, GT>>>(x, W1, N);
    gather_kernel<1><<<(N * 32 + T - 1) / T, T>>>(b1, N);
    gather_kernel<2><<<(N * 32 + T - 1) / T, T>>>(nullptr, N);
    final_kernel<<<(N + 127) / 128, 128>>>(W2, b2, out, N);
}